// round 11
// baseline (speedup 1.0000x reference)
#include <cuda_runtime.h>
#include <cuda_bf16.h>

// Problem constants (B=256, S=1024, H=128)
#define SEQ   1024
#define HID   128
#define NTHR  256            // 8 warps; lane pair = col halves of one unit
#define BPC   2              // batches per CTA
#define NCTA  128            // single wave on 148 SMs

#define XPAD  1032           // x row stride in floats
#define HROW  144            // bf16 elems per batch row: 64 + 8 pad + 64 + 8

// 16-byte vector of 4 bf16x2 (8 bf16 values)
struct __align__(16) bf16x8 { __nv_bfloat162 v[4]; };

// Single-MUFU transcendentals (sm_75+ tanh unit)
__device__ __forceinline__ float tanha(float x) {
    float y;
    asm("tanh.approx.f32 %0, %1;" : "=f"(y) : "f"(x));
    return y;
}
__device__ __forceinline__ float fsig(float s) {      // sigma(s) = 0.5*tanh(s/2)+0.5
    return fmaf(tanha(s * 0.5f), 0.5f, 0.5f);
}

__global__ void __launch_bounds__(NTHR, 1)
gru_fused_kernel(const float* __restrict__ x,     // [B, S]
                 const float* __restrict__ w_ih,  // [3H]
                 const float* __restrict__ w_hh,  // [3H, H]
                 const float* __restrict__ b_ih,  // [3H]
                 const float* __restrict__ b_hh,  // [3H]
                 const float* __restrict__ w_fc,  // [H]
                 const float* __restrict__ b_fc,  // [1]
                 float* __restrict__ out)         // [B]
{
    __shared__ __align__(16) float x_sh[BPC][XPAD];
    __shared__ __align__(16) __nv_bfloat16 h_sh[BPC][HROW];  // SINGLE-buffered h
    __shared__ __align__(16) float red_sh[BPC * HID];

    const int t    = threadIdx.x;
    const int b0   = blockIdx.x * BPC;
    const int u    = t >> 1;            // hidden unit owned by this lane pair
    const int half = t & 1;             // col half AND batch this lane finalizes

    // ---- weights: rows {u, u+128, u+256} x cols [half*64,+64), bf16x2 packed ----
    __nv_bfloat162 wr_[32], wz_[32], wn_[32];
    {
        const float4* pr = reinterpret_cast<const float4*>(w_hh + u * HID + half * 64);
        const float4* pz = reinterpret_cast<const float4*>(w_hh + (u + HID) * HID + half * 64);
        const float4* pn = reinterpret_cast<const float4*>(w_hh + (u + 2 * HID) * HID + half * 64);
        #pragma unroll
        for (int i = 0; i < 16; i++) {
            float4 a = pr[i];
            wr_[2*i]   = __floats2bfloat162_rn(a.x, a.y);
            wr_[2*i+1] = __floats2bfloat162_rn(a.z, a.w);
        }
        #pragma unroll
        for (int i = 0; i < 16; i++) {
            float4 a = pz[i];
            wz_[2*i]   = __floats2bfloat162_rn(a.x, a.y);
            wz_[2*i+1] = __floats2bfloat162_rn(a.z, a.w);
        }
        #pragma unroll
        for (int i = 0; i < 16; i++) {
            float4 a = pn[i];
            wn_[2*i]   = __floats2bfloat162_rn(a.x, a.y);
            wn_[2*i+1] = __floats2bfloat162_rn(a.z, a.w);
        }
    }

    // ---- per-lane gate constants (unit u), all fp32 ----
    const float Ar  = w_ih[u];
    const float Az  = w_ih[HID + u];
    const float An  = w_ih[2 * HID + u];
    const float Cr  = b_ih[u]         + b_hh[u];
    const float Cz  = b_ih[HID + u]   + b_hh[HID + u];
    const float Cni = b_ih[2 * HID + u];
    const float Cnh = b_hh[2 * HID + u];
    float hprev = 0.0f;                 // fp32 h[u] for batch `half`
    float pdr = 0.f, pdz = 0.f, pdn = 0.f;   // pending full dots (both lanes hold)

    // ---- stage x, zero h ----
    for (int i = t; i < SEQ; i += NTHR) {
        x_sh[0][i] = x[b0 * SEQ + i];
        x_sh[1][i] = x[(b0 + 1) * SEQ + i];
    }
    for (int i = t; i < BPC * HROW; i += NTHR)
        (&h_sh[0][0])[i] = __float2bfloat16(0.0f);
    __syncthreads();

    const int hwr = u + ((u & 64) >> 3);    // skewed write position for unit u

    // matvec partial dots for batch BAT over my column half -> fr,fz,fn
    #define MV_BODY(BAT, FR, FZ, FN)                                             \
        float FR, FZ, FN;                                                        \
        do {                                                                     \
            const bf16x8* hb =                                                   \
                reinterpret_cast<const bf16x8*>(&h_sh[BAT][half * 72]);          \
            __nv_bfloat162 AR[4], AZ[4], AN[4];                                  \
            __nv_bfloat162 zz = __float2bfloat162_rn(0.0f);                      \
            _Pragma("unroll")                                                    \
            for (int j = 0; j < 4; j++) { AR[j] = zz; AZ[j] = zz; AN[j] = zz; }  \
            _Pragma("unroll")                                                    \
            for (int i = 0; i < 8; i++) {                                        \
                bf16x8 v = hb[i];                                                \
                _Pragma("unroll")                                                \
                for (int j = 0; j < 4; j++) {                                    \
                    AR[j] = __hfma2(wr_[4*i+j], v.v[j], AR[j]);                  \
                    AZ[j] = __hfma2(wz_[4*i+j], v.v[j], AZ[j]);                  \
                    AN[j] = __hfma2(wn_[4*i+j], v.v[j], AN[j]);                  \
                }                                                                \
            }                                                                    \
            __nv_bfloat162 s2; float2 f2;                                        \
            s2 = __hadd2(__hadd2(AR[0],AR[1]), __hadd2(AR[2],AR[3]));            \
            f2 = __bfloat1622float2(s2); FR = f2.x + f2.y;                       \
            s2 = __hadd2(__hadd2(AZ[0],AZ[1]), __hadd2(AZ[2],AZ[3]));            \
            f2 = __bfloat1622float2(s2); FZ = f2.x + f2.y;                       \
            s2 = __hadd2(__hadd2(AN[0],AN[1]), __hadd2(AN[2],AN[3]));            \
            f2 = __bfloat1622float2(s2); FN = f2.x + f2.y;                       \
        } while (0)

    // combine halves: full dot lands on BOTH lanes (symmetric xor exchange)
    #define MV_FINISH(FR, FZ, FN)                                                \
        do {                                                                     \
            pdr = FR + __shfl_xor_sync(0xffffffffu, FR, 1);                      \
            pdz = FZ + __shfl_xor_sync(0xffffffffu, FZ, 1);                      \
            pdn = FN + __shfl_xor_sync(0xffffffffu, FN, 1);                      \
        } while (0)

    // gate tail for batch BAT at step SIDX; active only on its finalizing lane
    #define TAIL(BAT, SIDX)                                                      \
        do {                                                                     \
            if (half == (BAT)) {                                                 \
                float xv = x_sh[BAT][SIDX];                                      \
                float r  = fsig(fmaf(xv, Ar, Cr) + pdr);                         \
                float z  = fsig(fmaf(xv, Az, Cz) + pdz);                         \
                float n  = tanha(fmaf(xv, An, Cni) + r * (pdn + Cnh));           \
                hprev = n + z * (hprev - n);                                     \
                h_sh[BAT][hwr] = __float2bfloat16(hprev);                        \
            }                                                                    \
        } while (0)

    // ---- prologue: matvec b0@0 (h=0 staged above) ----
    {
        MV_BODY(0, fr, fz, fn);
        MV_FINISH(fr, fz, fn);
    }
    __syncthreads();

    for (int s = 0; s < SEQ; s++) {
        // Region B: matvec b1@s  ||  tail b0@s (uses pend from prev region A)
        {
            MV_BODY(1, fr, fz, fn);     // independent of TAIL below
            TAIL(0, s);                 // reads OLD pdr/pdz/pdn, writes h0[s+1]
            MV_FINISH(fr, fz, fn);      // overwrite pend with b1 dots
        }
        __syncthreads();                // h0[s+1] visible; b1 reads done

        // Region A: matvec b0@(s+1)  ||  tail b1@s
        if (s + 1 < SEQ) {
            MV_BODY(0, fr, fz, fn);
            TAIL(1, s);                 // reads b1 pend, writes h1[s+1]
            MV_FINISH(fr, fz, fn);
        } else {
            TAIL(1, s);
        }
        __syncthreads();                // h1[s+1] visible; b0 reads done
    }

    // ---- fused fc1: out[b] = relu(hT) . w_fc + b_fc (fp32 h state) ----
    red_sh[half * HID + u] = fmaxf(hprev, 0.0f) * w_fc[u];
    __syncthreads();
    if (t < BPC) {
        float acc = b_fc[0];
        #pragma unroll 8
        for (int k = 0; k < HID; k++)
            acc += red_sh[t * HID + k];
        out[b0 + t] = acc;
    }
}

extern "C" void kernel_launch(void* const* d_in, const int* in_sizes, int n_in,
                              void* d_out, int out_size) {
    const float* x    = (const float*)d_in[0];
    const float* w_ih = (const float*)d_in[1];
    const float* w_hh = (const float*)d_in[2];
    const float* b_ih = (const float*)d_in[3];
    const float* b_hh = (const float*)d_in[4];
    const float* w_fc = (const float*)d_in[5];
    const float* b_fc = (const float*)d_in[6];
    float* out = (float*)d_out;

    gru_fused_kernel<<<NCTA, NTHR>>>(x, w_ih, w_hh, b_ih, b_hh, w_fc, b_fc, out);
}

// round 12
// speedup vs baseline: 1.3159x; 1.3159x over previous
#include <cuda_runtime.h>
#include <cuda_bf16.h>

// Problem constants (B=256, S=1024, H=128)
#define SEQ   1024
#define HID   128
#define NTHR  128            // 4 warps; thread t owns unit t (all 3 gate rows)
#define NCTA  256            // 1 batch per CTA; 2 CTAs co-resident per SM

// 16-byte vector of 4 bf16x2 (8 bf16 values)
struct __align__(16) bf16x8 { __nv_bfloat162 v[4]; };

// Single-MUFU transcendentals (sm_75+ tanh unit)
__device__ __forceinline__ float tanha(float x) {
    float y;
    asm("tanh.approx.f32 %0, %1;" : "=f"(y) : "f"(x));
    return y;
}
__device__ __forceinline__ float fsig(float s) {      // sigma(s) = 0.5*tanh(s/2)+0.5
    return fmaf(tanha(s * 0.5f), 0.5f, 0.5f);
}

__global__ void __launch_bounds__(NTHR, 2)
gru_fused_kernel(const float* __restrict__ x,     // [B, S]
                 const float* __restrict__ w_ih,  // [3H]
                 const float* __restrict__ w_hh,  // [3H, H]
                 const float* __restrict__ b_ih,  // [3H]
                 const float* __restrict__ b_hh,  // [3H]
                 const float* __restrict__ w_fc,  // [H]
                 const float* __restrict__ b_fc,  // [1]
                 float* __restrict__ out)         // [B]
{
    __shared__ __align__(16) float x_sh[SEQ];                 // 4 KB
    __shared__ __align__(16) __nv_bfloat16 h_sh[2][HID];      // double-buffered bf16 h
    __shared__ __align__(16) float red_sh[HID];

    const int t = threadIdx.x;        // unit index
    const int b = blockIdx.x;         // batch index

    // ---- weights: rows {t, t+128, t+256}, ALL 128 cols, bf16x2 packed ----
    // 3 x 64 x 32-bit = 192 registers
    __nv_bfloat162 wr_[64], wz_[64], wn_[64];
    {
        const float4* pr = reinterpret_cast<const float4*>(w_hh + t * HID);
        const float4* pz = reinterpret_cast<const float4*>(w_hh + (t + HID) * HID);
        const float4* pn = reinterpret_cast<const float4*>(w_hh + (t + 2 * HID) * HID);
        #pragma unroll
        for (int i = 0; i < 32; i++) {
            float4 a = pr[i];
            wr_[2*i]   = __floats2bfloat162_rn(a.x, a.y);
            wr_[2*i+1] = __floats2bfloat162_rn(a.z, a.w);
        }
        #pragma unroll
        for (int i = 0; i < 32; i++) {
            float4 a = pz[i];
            wz_[2*i]   = __floats2bfloat162_rn(a.x, a.y);
            wz_[2*i+1] = __floats2bfloat162_rn(a.z, a.w);
        }
        #pragma unroll
        for (int i = 0; i < 32; i++) {
            float4 a = pn[i];
            wn_[2*i]   = __floats2bfloat162_rn(a.x, a.y);
            wn_[2*i+1] = __floats2bfloat162_rn(a.z, a.w);
        }
    }

    // ---- per-thread gate constants (unit t), all fp32 ----
    const float Ar  = w_ih[t];
    const float Az  = w_ih[HID + t];
    const float An  = w_ih[2 * HID + t];
    const float Cr  = b_ih[t]         + b_hh[t];
    const float Cz  = b_ih[HID + t]   + b_hh[HID + t];
    const float Cni = b_ih[2 * HID + t];
    const float Cnh = b_hh[2 * HID + t];
    float hprev = 0.0f;               // fp32 h[t] for this batch

    // ---- stage x, zero h buffer 0 ----
    for (int i = t; i < SEQ; i += NTHR)
        x_sh[i] = x[b * SEQ + i];
    h_sh[0][t] = __float2bfloat16(0.0f);
    __syncthreads();

    for (int s = 0; s < SEQ; s++) {
        const int rb = s & 1;
        const bf16x8* hb = reinterpret_cast<const bf16x8*>(h_sh[rb]);

        // 4 accumulation chains per gate (depth 16), bf16x2
        __nv_bfloat162 AR[4], AZ[4], AN[4];
        {
            __nv_bfloat162 zz = __float2bfloat162_rn(0.0f);
            #pragma unroll
            for (int j = 0; j < 4; j++) { AR[j] = zz; AZ[j] = zz; AN[j] = zz; }
        }
        #pragma unroll
        for (int i = 0; i < 16; i++) {
            bf16x8 v = hb[i];             // broadcast LDS.128 (conflict-free)
            #pragma unroll
            for (int j = 0; j < 4; j++) {
                AR[j] = __hfma2(wr_[4*i+j], v.v[j], AR[j]);
                AZ[j] = __hfma2(wz_[4*i+j], v.v[j], AZ[j]);
                AN[j] = __hfma2(wn_[4*i+j], v.v[j], AN[j]);
            }
        }
        float d_r, d_z, d_n;
        {
            __nv_bfloat162 s2; float2 f2;
            s2 = __hadd2(__hadd2(AR[0], AR[1]), __hadd2(AR[2], AR[3]));
            f2 = __bfloat1622float2(s2); d_r = f2.x + f2.y;
            s2 = __hadd2(__hadd2(AZ[0], AZ[1]), __hadd2(AZ[2], AZ[3]));
            f2 = __bfloat1622float2(s2); d_z = f2.x + f2.y;
            s2 = __hadd2(__hadd2(AN[0], AN[1]), __hadd2(AN[2], AN[3]));
            f2 = __bfloat1622float2(s2); d_n = f2.x + f2.y;
        }

        // ---- gates, fully thread-local, fp32 ----
        float xv = x_sh[s];
        float r  = fsig(fmaf(xv, Ar, Cr) + d_r);
        float z  = fsig(fmaf(xv, Az, Cz) + d_z);
        float n  = tanha(fmaf(xv, An, Cni) + r * (d_n + Cnh));
        hprev = n + z * (hprev - n);
        h_sh[rb ^ 1][t] = __float2bfloat16(hprev);   // write NEXT buffer
        __syncthreads();                             // single barrier per step
    }

    // ---- fused fc1: out[b] = relu(hT) . w_fc + b_fc ----
    red_sh[t] = fmaxf(hprev, 0.0f) * w_fc[t];
    __syncthreads();
    if (t < 32) {
        float acc = red_sh[t] + red_sh[t + 32] + red_sh[t + 64] + red_sh[t + 96];
        #pragma unroll
        for (int off = 16; off; off >>= 1)
            acc += __shfl_xor_sync(0xffffffffu, acc, off);
        if (t == 0)
            out[b] = acc + b_fc[0];
    }
}

extern "C" void kernel_launch(void* const* d_in, const int* in_sizes, int n_in,
                              void* d_out, int out_size) {
    const float* x    = (const float*)d_in[0];
    const float* w_ih = (const float*)d_in[1];
    const float* w_hh = (const float*)d_in[2];
    const float* b_ih = (const float*)d_in[3];
    const float* b_hh = (const float*)d_in[4];
    const float* w_fc = (const float*)d_in[5];
    const float* b_fc = (const float*)d_in[6];
    float* out = (float*)d_out;

    gru_fused_kernel<<<NCTA, NTHR>>>(x, w_ih, w_hh, b_ih, b_hh, w_fc, b_fc, out);
}

// round 13
// speedup vs baseline: 1.3352x; 1.0147x over previous
#include <cuda_runtime.h>
#include <cuda_bf16.h>

// Problem constants (B=256, S=1024, H=128)
#define SEQ   1024
#define HID   128
#define NTHR  128            // 4 warps; thread t owns unit t (all 3 gate rows)
#define NCTA  256            // 1 batch per CTA; 2 CTAs co-resident per SM

// 16-byte vector of 4 bf16x2 (8 bf16 values)
struct __align__(16) bf16x8 { __nv_bfloat162 v[4]; };

// Single-MUFU transcendentals (sm_75+ tanh unit)
__device__ __forceinline__ float tanha(float x) {
    float y;
    asm("tanh.approx.f32 %0, %1;" : "=f"(y) : "f"(x));
    return y;
}
__device__ __forceinline__ float fsig(float s) {      // sigma(s) = 0.5*tanh(s/2)+0.5
    return fmaf(tanha(s * 0.5f), 0.5f, 0.5f);
}

__global__ void __launch_bounds__(NTHR, 2)
gru_fused_kernel(const float* __restrict__ x,     // [B, S]
                 const float* __restrict__ w_ih,  // [3H]
                 const float* __restrict__ w_hh,  // [3H, H]
                 const float* __restrict__ b_ih,  // [3H]
                 const float* __restrict__ b_hh,  // [3H]
                 const float* __restrict__ w_fc,  // [H]
                 const float* __restrict__ b_fc,  // [1]
                 float* __restrict__ out)         // [B]
{
    __shared__ __align__(16) float x_sh[SEQ];                 // 4 KB
    __shared__ __align__(16) __nv_bfloat16 h_sh[2][HID];      // double-buffered bf16 h
    __shared__ __align__(16) float red_sh[HID];

    const int t = threadIdx.x;        // unit index
    const int b = blockIdx.x;         // batch index

    // ---- weights: rows {t, t+128, t+256}, ALL 128 cols, bf16x2 packed ----
    // 3 x 64 x 32-bit = 192 registers
    __nv_bfloat162 wr_[64], wz_[64], wn_[64];
    {
        const float4* pr = reinterpret_cast<const float4*>(w_hh + t * HID);
        const float4* pz = reinterpret_cast<const float4*>(w_hh + (t + HID) * HID);
        const float4* pn = reinterpret_cast<const float4*>(w_hh + (t + 2 * HID) * HID);
        #pragma unroll
        for (int i = 0; i < 32; i++) {
            float4 a = pr[i];
            wr_[2*i]   = __floats2bfloat162_rn(a.x, a.y);
            wr_[2*i+1] = __floats2bfloat162_rn(a.z, a.w);
        }
        #pragma unroll
        for (int i = 0; i < 32; i++) {
            float4 a = pz[i];
            wz_[2*i]   = __floats2bfloat162_rn(a.x, a.y);
            wz_[2*i+1] = __floats2bfloat162_rn(a.z, a.w);
        }
        #pragma unroll
        for (int i = 0; i < 32; i++) {
            float4 a = pn[i];
            wn_[2*i]   = __floats2bfloat162_rn(a.x, a.y);
            wn_[2*i+1] = __floats2bfloat162_rn(a.z, a.w);
        }
    }

    // ---- per-thread gate constants (unit t), all fp32 ----
    const float Ar  = w_ih[t];
    const float Az  = w_ih[HID + t];
    const float An  = w_ih[2 * HID + t];
    const float Cr  = b_ih[t]         + b_hh[t];
    const float Cz  = b_ih[HID + t]   + b_hh[HID + t];
    const float Cni = b_ih[2 * HID + t];
    const float Cnh = b_hh[2 * HID + t];
    float hprev = 0.0f;               // fp32 h[t] for this batch

    // ---- stage x, zero h buffer 0 ----
    for (int i = t; i < SEQ; i += NTHR)
        x_sh[i] = x[b * SEQ + i];
    h_sh[0][t] = __float2bfloat16(0.0f);
    __syncthreads();

    for (int s = 0; s < SEQ; s++) {
        const int rb = s & 1;
        const bf16x8* hb = reinterpret_cast<const bf16x8*>(h_sh[rb]);

        // gi pre-activations (independent of matvec, hoisted off the tail)
        float xv  = x_sh[s];
        float gir = fmaf(xv, Ar, Cr);
        float giz = fmaf(xv, Az, Cz);
        float gin = fmaf(xv, An, Cni);

        // ===== loop 1: r and z gate dots (h loaded once) =====
        __nv_bfloat162 AR[4], AZ[4];
        {
            bf16x8 v = hb[0];
            #pragma unroll
            for (int j = 0; j < 4; j++) {
                AR[j] = __hmul2(wr_[j], v.v[j]);    // first iter: no zero-init
                AZ[j] = __hmul2(wz_[j], v.v[j]);
            }
        }
        #pragma unroll
        for (int i = 1; i < 16; i++) {
            bf16x8 v = hb[i];
            #pragma unroll
            for (int j = 0; j < 4; j++) {
                AR[j] = __hfma2(wr_[4*i+j], v.v[j], AR[j]);
                AZ[j] = __hfma2(wz_[4*i+j], v.v[j], AZ[j]);
            }
        }
        float d_r, d_z;
        {
            __nv_bfloat162 s2; float2 f2;
            s2 = __hadd2(__hadd2(AR[0], AR[1]), __hadd2(AR[2], AR[3]));
            f2 = __bfloat1622float2(s2); d_r = f2.x + f2.y;
            s2 = __hadd2(__hadd2(AZ[0], AZ[1]), __hadd2(AZ[2], AZ[3]));
            f2 = __bfloat1622float2(s2); d_z = f2.x + f2.y;
        }
        // sigma chains launch now; latency hides under loop 2
        float r = fsig(gir + d_r);
        float z = fsig(giz + d_z);

        // ===== loop 2: n gate dot (h reloaded; broadcast LDS is cheap) =====
        __nv_bfloat162 AN[4];
        {
            bf16x8 v = hb[0];
            #pragma unroll
            for (int j = 0; j < 4; j++)
                AN[j] = __hmul2(wn_[j], v.v[j]);
        }
        #pragma unroll
        for (int i = 1; i < 16; i++) {
            bf16x8 v = hb[i];
            #pragma unroll
            for (int j = 0; j < 4; j++)
                AN[j] = __hfma2(wn_[4*i+j], v.v[j], AN[j]);
        }
        float d_n;
        {
            __nv_bfloat162 s2 = __hadd2(__hadd2(AN[0], AN[1]), __hadd2(AN[2], AN[3]));
            float2 f2 = __bfloat1622float2(s2);
            d_n = f2.x + f2.y;
        }

        // ---- remaining tail: tanh + update (r, z already resolved) ----
        float n = tanha(gin + r * (d_n + Cnh));
        hprev = n + z * (hprev - n);
        h_sh[rb ^ 1][t] = __float2bfloat16(hprev);   // write NEXT buffer
        __syncthreads();                             // single barrier per step
    }

    // ---- fused fc1: out[b] = relu(hT) . w_fc + b_fc ----
    red_sh[t] = fmaxf(hprev, 0.0f) * w_fc[t];
    __syncthreads();
    if (t < 32) {
        float acc = red_sh[t] + red_sh[t + 32] + red_sh[t + 64] + red_sh[t + 96];
        #pragma unroll
        for (int off = 16; off; off >>= 1)
            acc += __shfl_xor_sync(0xffffffffu, acc, off);
        if (t == 0)
            out[b] = acc + b_fc[0];
    }
}

extern "C" void kernel_launch(void* const* d_in, const int* in_sizes, int n_in,
                              void* d_out, int out_size) {
    const float* x    = (const float*)d_in[0];
    const float* w_ih = (const float*)d_in[1];
    const float* w_hh = (const float*)d_in[2];
    const float* b_ih = (const float*)d_in[3];
    const float* b_hh = (const float*)d_in[4];
    const float* w_fc = (const float*)d_in[5];
    const float* b_fc = (const float*)d_in[6];
    float* out = (float*)d_out;

    gru_fused_kernel<<<NCTA, NTHR>>>(x, w_ih, w_hh, b_ih, b_hh, w_fc, b_fc, out);
}

// round 14
// speedup vs baseline: 1.3428x; 1.0057x over previous
#include <cuda_runtime.h>
#include <cuda_bf16.h>

// Problem constants (B=256, S=1024, H=128)
#define SEQ   1024
#define HID   128
#define NTHR  128            // 4 warps; thread t owns unit t (all 3 gate rows)
#define NCTA  256            // 1 batch per CTA; 2 CTAs co-resident per SM

// 16-byte vector of 4 bf16x2 (8 bf16 values)
struct __align__(16) bf16x8 { __nv_bfloat162 v[4]; };

// Single-MUFU transcendentals (sm_75+ tanh unit)
__device__ __forceinline__ float tanha(float x) {
    float y;
    asm("tanh.approx.f32 %0, %1;" : "=f"(y) : "f"(x));
    return y;
}
__device__ __forceinline__ float fsig(float s) {      // sigma(s) = 0.5*tanh(s/2)+0.5
    return fmaf(tanha(s * 0.5f), 0.5f, 0.5f);
}

__global__ void __launch_bounds__(NTHR, 2)
gru_fused_kernel(const float* __restrict__ x,     // [B, S]
                 const float* __restrict__ w_ih,  // [3H]
                 const float* __restrict__ w_hh,  // [3H, H]
                 const float* __restrict__ b_ih,  // [3H]
                 const float* __restrict__ b_hh,  // [3H]
                 const float* __restrict__ w_fc,  // [H]
                 const float* __restrict__ b_fc,  // [1]
                 float* __restrict__ out)         // [B]
{
    __shared__ __align__(16) float x_sh[SEQ];                 // 4 KB
    __shared__ __align__(16) __nv_bfloat16 h_sh[2][HID];      // double-buffered bf16 h
    __shared__ __align__(16) float red_sh[HID];

    const int t = threadIdx.x;        // unit index
    const int b = blockIdx.x;         // batch index

    // ---- anti-phase stagger: second-slot CTAs (wave-2 placement) delay ~480cyc
    // so their gate-tail phase interleaves with the co-resident CTA's matvec.
    if (b >= 148) {
        float d = 1.0f;
        #pragma unroll 1
        for (int i = 0; i < 120; i++)
            asm volatile("add.f32 %0, %0, 0f3F800000;" : "+f"(d));  // lat-4 chain
        // d == 121.0f always; consume it so it can never be elided
        if (__float_as_uint(d) == 0u) red_sh[0] = d;
    }

    // ---- weights: rows {t, t+128, t+256}, ALL 128 cols, bf16x2 packed ----
    // 3 x 64 x 32-bit = 192 registers
    __nv_bfloat162 wr_[64], wz_[64], wn_[64];
    {
        const float4* pr = reinterpret_cast<const float4*>(w_hh + t * HID);
        const float4* pz = reinterpret_cast<const float4*>(w_hh + (t + HID) * HID);
        const float4* pn = reinterpret_cast<const float4*>(w_hh + (t + 2 * HID) * HID);
        #pragma unroll
        for (int i = 0; i < 32; i++) {
            float4 a = pr[i];
            wr_[2*i]   = __floats2bfloat162_rn(a.x, a.y);
            wr_[2*i+1] = __floats2bfloat162_rn(a.z, a.w);
        }
        #pragma unroll
        for (int i = 0; i < 32; i++) {
            float4 a = pz[i];
            wz_[2*i]   = __floats2bfloat162_rn(a.x, a.y);
            wz_[2*i+1] = __floats2bfloat162_rn(a.z, a.w);
        }
        #pragma unroll
        for (int i = 0; i < 32; i++) {
            float4 a = pn[i];
            wn_[2*i]   = __floats2bfloat162_rn(a.x, a.y);
            wn_[2*i+1] = __floats2bfloat162_rn(a.z, a.w);
        }
    }

    // ---- per-thread gate constants (unit t), all fp32 ----
    const float Ar  = w_ih[t];
    const float Az  = w_ih[HID + t];
    const float An  = w_ih[2 * HID + t];
    const float Cr  = b_ih[t]         + b_hh[t];
    const float Cz  = b_ih[HID + t]   + b_hh[HID + t];
    const float Cni = b_ih[2 * HID + t];
    const float Cnh = b_hh[2 * HID + t];
    float hprev = 0.0f;               // fp32 h[t] for this batch

    // ---- stage x, zero h buffer 0 ----
    for (int i = t; i < SEQ; i += NTHR)
        x_sh[i] = x[b * SEQ + i];
    h_sh[0][t] = __float2bfloat16(0.0f);
    __syncthreads();

    for (int s = 0; s < SEQ; s++) {
        const int rb = s & 1;
        const bf16x8* hb = reinterpret_cast<const bf16x8*>(h_sh[rb]);

        // gi pre-activations (independent of matvec, hoisted off the tail)
        float xv  = x_sh[s];
        float gir = fmaf(xv, Ar, Cr);
        float giz = fmaf(xv, Az, Cz);
        float gin = fmaf(xv, An, Cni);

        // ===== loop 1: r and z gate dots (h loaded once) =====
        __nv_bfloat162 AR[4], AZ[4];
        {
            bf16x8 v = hb[0];
            #pragma unroll
            for (int j = 0; j < 4; j++) {
                AR[j] = __hmul2(wr_[j], v.v[j]);    // first iter: no zero-init
                AZ[j] = __hmul2(wz_[j], v.v[j]);
            }
        }
        #pragma unroll
        for (int i = 1; i < 16; i++) {
            bf16x8 v = hb[i];
            #pragma unroll
            for (int j = 0; j < 4; j++) {
                AR[j] = __hfma2(wr_[4*i+j], v.v[j], AR[j]);
                AZ[j] = __hfma2(wz_[4*i+j], v.v[j], AZ[j]);
            }
        }
        float d_r, d_z;
        {
            __nv_bfloat162 s2; float2 f2;
            s2 = __hadd2(__hadd2(AR[0], AR[1]), __hadd2(AR[2], AR[3]));
            f2 = __bfloat1622float2(s2); d_r = f2.x + f2.y;
            s2 = __hadd2(__hadd2(AZ[0], AZ[1]), __hadd2(AZ[2], AZ[3]));
            f2 = __bfloat1622float2(s2); d_z = f2.x + f2.y;
        }
        // sigma chains launch now; latency hides under loop 2
        float r = fsig(gir + d_r);
        float z = fsig(giz + d_z);

        // ===== loop 2: n gate dot (h reloaded; broadcast LDS is cheap) =====
        __nv_bfloat162 AN[4];
        {
            bf16x8 v = hb[0];
            #pragma unroll
            for (int j = 0; j < 4; j++)
                AN[j] = __hmul2(wn_[j], v.v[j]);
        }
        #pragma unroll
        for (int i = 1; i < 16; i++) {
            bf16x8 v = hb[i];
            #pragma unroll
            for (int j = 0; j < 4; j++)
                AN[j] = __hfma2(wn_[4*i+j], v.v[j], AN[j]);
        }
        float d_n;
        {
            __nv_bfloat162 s2 = __hadd2(__hadd2(AN[0], AN[1]), __hadd2(AN[2], AN[3]));
            float2 f2 = __bfloat1622float2(s2);
            d_n = f2.x + f2.y;
        }

        // ---- remaining tail: tanh + update (r, z already resolved) ----
        float n = tanha(gin + r * (d_n + Cnh));
        hprev = n + z * (hprev - n);
        h_sh[rb ^ 1][t] = __float2bfloat16(hprev);   // write NEXT buffer
        __syncthreads();                             // single barrier per step
    }

    // ---- fused fc1: out[b] = relu(hT) . w_fc + b_fc ----
    red_sh[t] = fmaxf(hprev, 0.0f) * w_fc[t];
    __syncthreads();
    if (t < 32) {
        float acc = red_sh[t] + red_sh[t + 32] + red_sh[t + 64] + red_sh[t + 96];
        #pragma unroll
        for (int off = 16; off; off >>= 1)
            acc += __shfl_xor_sync(0xffffffffu, acc, off);
        if (t == 0)
            out[b] = acc + b_fc[0];
    }
}

extern "C" void kernel_launch(void* const* d_in, const int* in_sizes, int n_in,
                              void* d_out, int out_size) {
    const float* x    = (const float*)d_in[0];
    const float* w_ih = (const float*)d_in[1];
    const float* w_hh = (const float*)d_in[2];
    const float* b_ih = (const float*)d_in[3];
    const float* b_hh = (const float*)d_in[4];
    const float* w_fc = (const float*)d_in[5];
    const float* b_fc = (const float*)d_in[6];
    float* out = (float*)d_out;

    gru_fused_kernel<<<NCTA, NTHR>>>(x, w_ih, w_hh, b_ih, b_hh, w_fc, b_fc, out);
}

// round 16
// speedup vs baseline: 1.9634x; 1.4622x over previous
#include <cuda_runtime.h>
#include <cuda_bf16.h>
#include <cstdint>

// Problem constants (B=256, S=1024, H=128)
#define SEQ   1024
#define HID   128
#define NB    2              // batches per CTA (occupy n-cols 0,1 of the n8 tile)
#define NCTA  128            // 1 CTA per SM (single wave on 148 SMs)
#define NTHR  256            // 8 warps; warp w owns rows [48w, 48w+48) = 3 m16 tiles
#define HPAD  136            // bf16 elements per h row (+8 pad -> conflict-free)

// Single-MUFU transcendentals (sm_75+ tanh unit)
__device__ __forceinline__ float tanha(float x) {
    float y;
    asm("tanh.approx.f32 %0, %1;" : "=f"(y) : "f"(x));
    return y;
}
__device__ __forceinline__ float fsig(float s) {   // sigma(s)=0.5*tanh(s/2)+0.5
    return fmaf(tanha(s * 0.5f), 0.5f, 0.5f);
}

__global__ void __launch_bounds__(NTHR, 1)
gru_fused_kernel(const float* __restrict__ x,     // [B, S]
                 const float* __restrict__ w_ih,  // [3H]
                 const float* __restrict__ w_hh,  // [3H, H]
                 const float* __restrict__ b_ih,  // [3H]
                 const float* __restrict__ b_hh,  // [3H]
                 const float* __restrict__ w_fc,  // [H]
                 const float* __restrict__ b_fc,  // [1]
                 float* __restrict__ out)         // [B]
{
    __shared__ __align__(16) float x_sh[NB][SEQ];             // 8 KB
    __shared__ __align__(16) __nv_bfloat16 h_sh[8][HPAD];     // B operand [n][k]
    __shared__ __align__(16) float gh_sh[3 * HID][NB];        // D redistribution
    __shared__ __align__(16) float red_sh[NB][HID];           // fc scratch

    const int t    = threadIdx.x;
    const int b0   = blockIdx.x * NB;
    const int w    = t >> 5;
    const int lane = t & 31;
    const int g    = lane >> 2;      // group id (row-within-tile / n-col)
    const int tg   = lane & 3;       // thread-in-group

    // ---- A fragments: warp w rows [48w,48w+48) x K=128, bf16, in registers ----
    // 3 m-tiles x 8 k-chunks x 4 regs = 96 regs/thread, loaded ONCE.
    uint32_t a_[3][8][4];
    #pragma unroll
    for (int mt = 0; mt < 3; mt++) {
        const int r0 = w * 48 + mt * 16 + g;
        #pragma unroll
        for (int kc = 0; kc < 8; kc++) {
            const float* p0 = w_hh + r0 * HID + kc * 16 + 2 * tg;
            const float* p1 = p0 + 8 * HID;              // row +8 in tile
            float2 v;
            __nv_bfloat162 q;
            v = *(const float2*)(p0);
            q = __floats2bfloat162_rn(v.x, v.y); a_[mt][kc][0] = *(uint32_t*)&q;
            v = *(const float2*)(p1);
            q = __floats2bfloat162_rn(v.x, v.y); a_[mt][kc][1] = *(uint32_t*)&q;
            v = *(const float2*)(p0 + 8);
            q = __floats2bfloat162_rn(v.x, v.y); a_[mt][kc][2] = *(uint32_t*)&q;
            v = *(const float2*)(p1 + 8);
            q = __floats2bfloat162_rn(v.x, v.y); a_[mt][kc][3] = *(uint32_t*)&q;
        }
    }

    // ---- per-thread gate constants: unit u, batch nb ----
    const int u  = t & (HID - 1);
    const int nb = t >> 7;
    const float Ar  = w_ih[u];
    const float Az  = w_ih[HID + u];
    const float An  = w_ih[2 * HID + u];
    const float Cr  = b_ih[u]         + b_hh[u];
    const float Cz  = b_ih[HID + u]   + b_hh[HID + u];
    const float Cni = b_ih[2 * HID + u];
    const float Cnh = b_hh[2 * HID + u];
    float hreg = 0.0f;               // h[u] for batch nb

    // ---- stage x; zero ALL 8 h rows (rows 2..7 stay zero forever) ----
    {
        const float4* xg = reinterpret_cast<const float4*>(x + b0 * SEQ);
        float4* xs = reinterpret_cast<float4*>(&x_sh[0][0]);
        for (int i = t; i < NB * SEQ / 4; i += NTHR)
            xs[i] = xg[i];
    }
    for (int i = t; i < 8 * HPAD; i += NTHR)
        (&h_sh[0][0])[i] = __float2bfloat16(0.0f);
    __syncthreads();

    for (int s = 0; s < SEQ; s++) {
        // ===== tensor matvec: D[384x8] = W[384x128] @ h[128x8] =====
        float c0_[3], c1_[3], c2_[3], c3_[3];
        #pragma unroll
        for (int mt = 0; mt < 3; mt++) {
            c0_[mt] = 0.f; c1_[mt] = 0.f; c2_[mt] = 0.f; c3_[mt] = 0.f;
        }
        #pragma unroll
        for (int kc = 0; kc < 8; kc++) {
            // B fragment (col-major 16x8): b0={B[2tg][g],B[2tg+1][g]}, b1=+8 rows
            uint32_t br0 = *(const uint32_t*)&h_sh[g][kc * 16 + 2 * tg];
            uint32_t br1 = *(const uint32_t*)&h_sh[g][kc * 16 + 2 * tg + 8];
            #pragma unroll
            for (int mt = 0; mt < 3; mt++) {
                asm volatile(
                    "mma.sync.aligned.m16n8k16.row.col.f32.bf16.bf16.f32 "
                    "{%0,%1,%2,%3}, {%4,%5,%6,%7}, {%8,%9}, {%0,%1,%2,%3};"
                    : "+f"(c0_[mt]), "+f"(c1_[mt]), "+f"(c2_[mt]), "+f"(c3_[mt])
                    : "r"(a_[mt][kc][0]), "r"(a_[mt][kc][1]),
                      "r"(a_[mt][kc][2]), "r"(a_[mt][kc][3]),
                      "r"(br0), "r"(br1));
            }
        }
        // redistribute: tg==0 lanes hold n-cols {0,1} = our two batches
        if (tg == 0) {
            #pragma unroll
            for (int mt = 0; mt < 3; mt++) {
                const int r = w * 48 + mt * 16 + g;
                *(float2*)&gh_sh[r][0]     = make_float2(c0_[mt], c1_[mt]);
                *(float2*)&gh_sh[r + 8][0] = make_float2(c2_[mt], c3_[mt]);
            }
        }
        __syncthreads();

        // ===== gates: thread handles (unit u, batch nb) =====
        {
            float xv = x_sh[nb][s];
            float dr = gh_sh[u][nb];
            float dz = gh_sh[HID + u][nb];
            float dn = gh_sh[2 * HID + u][nb];
            float r  = fsig(fmaf(xv, Ar, Cr) + dr);
            float z  = fsig(fmaf(xv, Az, Cz) + dz);
            float n  = tanha(fmaf(xv, An, Cni) + r * (dn + Cnh));
            hreg = n + z * (hreg - n);
            h_sh[nb][u] = __float2bfloat16(hreg);
        }
        __syncthreads();
    }

    // ---- fused fc1: out[b] = relu(hT) . w_fc + b_fc ----
    red_sh[nb][u] = fmaxf(hreg, 0.0f) * w_fc[u];
    __syncthreads();
    if (w < NB) {
        float acc = red_sh[w][lane] + red_sh[w][lane + 32] +
                    red_sh[w][lane + 64] + red_sh[w][lane + 96];
        #pragma unroll
        for (int off = 16; off; off >>= 1)
            acc += __shfl_xor_sync(0xffffffffu, acc, off);
        if (lane == 0)
            out[b0 + w] = acc + b_fc[0];
    }
}

extern "C" void kernel_launch(void* const* d_in, const int* in_sizes, int n_in,
                              void* d_out, int out_size) {
    const float* x    = (const float*)d_in[0];
    const float* w_ih = (const float*)d_in[1];
    const float* w_hh = (const float*)d_in[2];
    const float* b_ih = (const float*)d_in[3];
    const float* b_hh = (const float*)d_in[4];
    const float* w_fc = (const float*)d_in[5];
    const float* b_fc = (const float*)d_in[6];
    float* out = (float*)d_out;

    gru_fused_kernel<<<NCTA, NTHR>>>(x, w_ih, w_hh, b_ih, b_hh, w_fc, b_fc, out);
}